// round 1
// baseline (speedup 1.0000x reference)
#include <cuda_runtime.h>

#define NN_MAX 60000
#define EE_MAX 960000

// ---------------- scratch (static device allocations; no cudaMalloc) ----------------
__device__ float g_asrc[NN_MAX * 64];
__device__ float g_adst[NN_MAX * 64];
__device__ float g_v[NN_MAX * 64];
__device__ float g_nd[NN_MAX * 128];   // [node][0:64]=numerator, [64:128]=denominator

// ================= node kernel: h=relu(xWin+bin); a_src,a_dst,v; zero nd =================
struct NodeSmem {
    float Win[64 * 64], Ws[64 * 64], Wd[64 * 64], Wl[64 * 64];
    float bin[64], bl[64];
    float xs[8][64];
    float hs[8][64];
};

__global__ __launch_bounds__(256, 3) void node_kernel(
    const float* __restrict__ x,
    const float* __restrict__ Win, const float* __restrict__ bin,
    const float* __restrict__ Wsrc, const float* __restrict__ Wdst,
    const float* __restrict__ Wlin, const float* __restrict__ blin, int nn)
{
    extern __shared__ char smem_raw[];
    NodeSmem& s = *reinterpret_cast<NodeSmem*>(smem_raw);
    int tid = threadIdx.x;
    for (int i = tid; i < 4096; i += blockDim.x) {
        s.Win[i] = Win[i]; s.Ws[i] = Wsrc[i]; s.Wd[i] = Wdst[i]; s.Wl[i] = Wlin[i];
    }
    if (tid < 64) { s.bin[tid] = bin[tid]; s.bl[tid] = blin[tid]; }
    __syncthreads();

    int warp = tid >> 5, lane = tid & 31, c0 = lane * 2;
    int totW = (gridDim.x * blockDim.x) >> 5;
    for (int node = (blockIdx.x * blockDim.x + tid) >> 5; node < nn; node += totW) {
        float2 xv = *reinterpret_cast<const float2*>(&x[node * 64 + c0]);
        s.xs[warp][c0] = xv.x; s.xs[warp][c0 + 1] = xv.y;
        __syncwarp();
        float h0 = s.bin[c0], h1 = s.bin[c0 + 1];
        #pragma unroll 16
        for (int k = 0; k < 64; k++) {
            float xk = s.xs[warp][k];
            float2 w = *reinterpret_cast<float2*>(&s.Win[k * 64 + c0]);
            h0 = fmaf(xk, w.x, h0); h1 = fmaf(xk, w.y, h1);
        }
        h0 = fmaxf(h0, 0.f); h1 = fmaxf(h1, 0.f);
        __syncwarp();
        s.hs[warp][c0] = h0; s.hs[warp][c0 + 1] = h1;
        __syncwarp();
        float s0 = 0.f, s1 = 0.f, d0 = 0.f, d1 = 0.f;
        float v0 = s.bl[c0], v1 = s.bl[c0 + 1];
        #pragma unroll 16
        for (int k = 0; k < 64; k++) {
            float hk = s.hs[warp][k];
            float2 ws = *reinterpret_cast<float2*>(&s.Ws[k * 64 + c0]);
            float2 wd = *reinterpret_cast<float2*>(&s.Wd[k * 64 + c0]);
            float2 wl = *reinterpret_cast<float2*>(&s.Wl[k * 64 + c0]);
            s0 = fmaf(hk, ws.x, s0); s1 = fmaf(hk, ws.y, s1);
            d0 = fmaf(hk, wd.x, d0); d1 = fmaf(hk, wd.y, d1);
            v0 = fmaf(hk, wl.x, v0); v1 = fmaf(hk, wl.y, v1);
        }
        *reinterpret_cast<float2*>(&g_asrc[node * 64 + c0]) = make_float2(s0, s1);
        *reinterpret_cast<float2*>(&g_adst[node * 64 + c0]) = make_float2(d0, d1);
        *reinterpret_cast<float2*>(&g_v[node * 64 + c0])    = make_float2(v0, v1);
        *reinterpret_cast<float4*>(&g_nd[node * 128 + lane * 4]) = make_float4(0.f, 0.f, 0.f, 0.f);
        __syncwarp();
    }
}

// ================= edge kernel: fused delta-MLP, attn-MLP, exp, RED accumulate =================
#define NWARP 8
#define ME 8

struct EdgeSmem {
    float Wp1[3 * 64];
    float Wp2[64 * 64], Wa1[64 * 64], Wa2[64 * 64];
    float bp1[64], bp2[64], ba1[64], ba2[64];
    float X[NWARP][ME][64];   // h1 -> q -> t (reused between syncwarps)
    float D[NWARP][ME][64];   // delta
    int   srcs[NWARP][ME];
    int   dsts[NWARP][ME];
    float pd[NWARP][ME][3];
};

__global__ __launch_bounds__(256, 2) void edge_kernel(
    const float* __restrict__ pos, const int* __restrict__ ei,
    const float* __restrict__ Wp1, const float* __restrict__ bp1,
    const float* __restrict__ Wp2, const float* __restrict__ bp2,
    const float* __restrict__ Wa1, const float* __restrict__ ba1,
    const float* __restrict__ Wa2, const float* __restrict__ ba2, int ne)
{
    extern __shared__ char smem_raw[];
    EdgeSmem& s = *reinterpret_cast<EdgeSmem*>(smem_raw);
    int tid = threadIdx.x;
    for (int i = tid; i < 3 * 64; i += blockDim.x) s.Wp1[i] = Wp1[i];
    for (int i = tid; i < 4096; i += blockDim.x) {
        s.Wp2[i] = Wp2[i]; s.Wa1[i] = Wa1[i]; s.Wa2[i] = Wa2[i];
    }
    if (tid < 64) { s.bp1[tid] = bp1[tid]; s.bp2[tid] = bp2[tid]; s.ba1[tid] = ba1[tid]; s.ba2[tid] = ba2[tid]; }
    __syncthreads();

    int warp = tid >> 5, lane = tid & 31, c0 = lane * 2;
    int gw = blockIdx.x * NWARP + warp;
    int totW = gridDim.x * NWARP;
    int ngroups = (ne + ME - 1) / ME;

    for (int g = gw; g < ngroups; g += totW) {
        int e0 = g * ME;
        // ---- per-edge meta: indices + pos diff ----
        if (lane < ME) {
            int eidx = e0 + lane;
            int si = 0, di = 0;
            float p0 = 0.f, p1 = 0.f, p2 = 0.f;
            if (eidx < ne) {
                si = ei[eidx];
                di = ei[ne + eidx];
                p0 = pos[di * 3 + 0] - pos[si * 3 + 0];
                p1 = pos[di * 3 + 1] - pos[si * 3 + 1];
                p2 = pos[di * 3 + 2] - pos[si * 3 + 2];
            }
            s.srcs[warp][lane] = si; s.dsts[warp][lane] = di;
            s.pd[warp][lane][0] = p0; s.pd[warp][lane][1] = p1; s.pd[warp][lane][2] = p2;
        }
        __syncwarp();

        // ---- h1 = relu(pd @ Wp1 + bp1) ----
        {
            float b0 = s.bp1[c0], b1 = s.bp1[c0 + 1];
            float2 w0 = *reinterpret_cast<float2*>(&s.Wp1[0 * 64 + c0]);
            float2 w1 = *reinterpret_cast<float2*>(&s.Wp1[1 * 64 + c0]);
            float2 w2 = *reinterpret_cast<float2*>(&s.Wp1[2 * 64 + c0]);
            #pragma unroll
            for (int e = 0; e < ME; e++) {
                float p0 = s.pd[warp][e][0], p1 = s.pd[warp][e][1], p2 = s.pd[warp][e][2];
                float a0 = fmaf(p2, w2.x, fmaf(p1, w1.x, fmaf(p0, w0.x, b0)));
                float a1 = fmaf(p2, w2.y, fmaf(p1, w1.y, fmaf(p0, w0.y, b1)));
                s.X[warp][e][c0] = fmaxf(a0, 0.f);
                s.X[warp][e][c0 + 1] = fmaxf(a1, 0.f);
            }
        }
        // prefetch a_dst[dst], a_src[src] gathers (independent of delta matvec)
        float2 ad[ME], as[ME];
        #pragma unroll
        for (int e = 0; e < ME; e++) {
            int si = s.srcs[warp][e], di = s.dsts[warp][e];
            ad[e] = *reinterpret_cast<const float2*>(&g_adst[di * 64 + c0]);
            as[e] = *reinterpret_cast<const float2*>(&g_asrc[si * 64 + c0]);
        }
        __syncwarp();

        // ---- delta = relu(h1 @ Wp2 + bp2) ----
        float acc0[ME], acc1[ME];
        #pragma unroll
        for (int e = 0; e < ME; e++) { acc0[e] = 0.f; acc1[e] = 0.f; }
        #pragma unroll 8
        for (int k = 0; k < 64; k++) {
            float2 w = *reinterpret_cast<float2*>(&s.Wp2[k * 64 + c0]);
            #pragma unroll
            for (int e = 0; e < ME; e++) {
                float xk = s.X[warp][e][k];
                acc0[e] = fmaf(xk, w.x, acc0[e]);
                acc1[e] = fmaf(xk, w.y, acc1[e]);
            }
        }
        __syncwarp();
        #pragma unroll
        for (int e = 0; e < ME; e++) {
            float d0 = fmaxf(acc0[e] + s.bp2[c0], 0.f);
            float d1 = fmaxf(acc1[e] + s.bp2[c0 + 1], 0.f);
            s.D[warp][e][c0] = d0;  s.D[warp][e][c0 + 1] = d1;
            s.X[warp][e][c0]     = ad[e].x - as[e].x + d0;
            s.X[warp][e][c0 + 1] = ad[e].y - as[e].y + d1;
        }
        __syncwarp();

        // ---- t = relu(q @ Wa1 + ba1) ----
        #pragma unroll
        for (int e = 0; e < ME; e++) { acc0[e] = 0.f; acc1[e] = 0.f; }
        #pragma unroll 8
        for (int k = 0; k < 64; k++) {
            float2 w = *reinterpret_cast<float2*>(&s.Wa1[k * 64 + c0]);
            #pragma unroll
            for (int e = 0; e < ME; e++) {
                float xk = s.X[warp][e][k];
                acc0[e] = fmaf(xk, w.x, acc0[e]);
                acc1[e] = fmaf(xk, w.y, acc1[e]);
            }
        }
        __syncwarp();
        #pragma unroll
        for (int e = 0; e < ME; e++) {
            s.X[warp][e][c0]     = fmaxf(acc0[e] + s.ba1[c0], 0.f);
            s.X[warp][e][c0 + 1] = fmaxf(acc1[e] + s.ba1[c0 + 1], 0.f);
        }
        __syncwarp();

        // prefetch v[src]
        float2 vv[ME];
        #pragma unroll
        for (int e = 0; e < ME; e++) {
            int si = s.srcs[warp][e];
            vv[e] = *reinterpret_cast<const float2*>(&g_v[si * 64 + c0]);
        }

        // ---- a = relu(t @ Wa2 + ba2); p = exp(a); accumulate ----
        #pragma unroll
        for (int e = 0; e < ME; e++) { acc0[e] = 0.f; acc1[e] = 0.f; }
        #pragma unroll 8
        for (int k = 0; k < 64; k++) {
            float2 w = *reinterpret_cast<float2*>(&s.Wa2[k * 64 + c0]);
            #pragma unroll
            for (int e = 0; e < ME; e++) {
                float xk = s.X[warp][e][k];
                acc0[e] = fmaf(xk, w.x, acc0[e]);
                acc1[e] = fmaf(xk, w.y, acc1[e]);
            }
        }
        #pragma unroll
        for (int e = 0; e < ME; e++) {
            if (e0 + e < ne) {
                float a0 = fmaxf(acc0[e] + s.ba2[c0], 0.f);
                float a1 = fmaxf(acc1[e] + s.ba2[c0 + 1], 0.f);
                float p0 = __expf(a0), p1 = __expf(a1);
                float w0v = vv[e].x + s.D[warp][e][c0];
                float w1v = vv[e].y + s.D[warp][e][c0 + 1];
                int di = s.dsts[warp][e];
                float* nd = &g_nd[di * 128];
                atomicAdd(&nd[c0],      p0 * w0v);
                atomicAdd(&nd[c0 + 1],  p1 * w1v);
                atomicAdd(&nd[64 + c0],     p0);
                atomicAdd(&nd[64 + c0 + 1], p1);
            }
        }
        __syncwarp();   // protect meta/X/D reuse across group iterations
    }
}

// ================= out kernel: relu((num/den) @ W_out + b_out) =================
struct OutSmem {
    float W[64 * 64];
    float b[64];
    float rs[8][64];
};

__global__ __launch_bounds__(256, 3) void out_kernel(
    const float* __restrict__ Wout, const float* __restrict__ bout,
    float* __restrict__ out, int nn)
{
    extern __shared__ char smem_raw[];
    OutSmem& s = *reinterpret_cast<OutSmem*>(smem_raw);
    int tid = threadIdx.x;
    for (int i = tid; i < 4096; i += blockDim.x) s.W[i] = Wout[i];
    if (tid < 64) s.b[tid] = bout[tid];
    __syncthreads();

    int warp = tid >> 5, lane = tid & 31, c0 = lane * 2;
    int totW = (gridDim.x * blockDim.x) >> 5;
    for (int node = (blockIdx.x * blockDim.x + tid) >> 5; node < nn; node += totW) {
        float2 nm = *reinterpret_cast<float2*>(&g_nd[node * 128 + c0]);
        float2 dn = *reinterpret_cast<float2*>(&g_nd[node * 128 + 64 + c0]);
        float r0 = nm.x / (dn.x + 1e-16f);
        float r1 = nm.y / (dn.y + 1e-16f);
        s.rs[warp][c0] = r0; s.rs[warp][c0 + 1] = r1;
        __syncwarp();
        float o0 = s.b[c0], o1 = s.b[c0 + 1];
        #pragma unroll 16
        for (int k = 0; k < 64; k++) {
            float rk = s.rs[warp][k];
            float2 w = *reinterpret_cast<float2*>(&s.W[k * 64 + c0]);
            o0 = fmaf(rk, w.x, o0); o1 = fmaf(rk, w.y, o1);
        }
        *reinterpret_cast<float2*>(&out[node * 64 + c0]) =
            make_float2(fmaxf(o0, 0.f), fmaxf(o1, 0.f));
        __syncwarp();
    }
}

// ================= launch =================
extern "C" void kernel_launch(void* const* d_in, const int* in_sizes, int n_in,
                              void* d_out, int out_size)
{
    const float* x     = (const float*)d_in[0];
    const float* pos   = (const float*)d_in[1];
    const float* W_in  = (const float*)d_in[2];
    const float* b_in  = (const float*)d_in[3];
    const float* W_src = (const float*)d_in[4];
    const float* W_dst = (const float*)d_in[5];
    const float* W_lin = (const float*)d_in[6];
    const float* b_lin = (const float*)d_in[7];
    const float* Wp1   = (const float*)d_in[8];
    const float* bp1   = (const float*)d_in[9];
    const float* Wp2   = (const float*)d_in[10];
    const float* bp2   = (const float*)d_in[11];
    const float* Wa1   = (const float*)d_in[12];
    const float* ba1   = (const float*)d_in[13];
    const float* Wa2   = (const float*)d_in[14];
    const float* ba2   = (const float*)d_in[15];
    const float* W_out = (const float*)d_in[16];
    const float* b_out = (const float*)d_in[17];
    const int*   ei    = (const int*)d_in[18];
    float* out = (float*)d_out;

    int nn = in_sizes[0] / 64;
    int ne = in_sizes[18] / 2;

    cudaFuncSetAttribute(node_kernel, cudaFuncAttributeMaxDynamicSharedMemorySize, (int)sizeof(NodeSmem));
    cudaFuncSetAttribute(edge_kernel, cudaFuncAttributeMaxDynamicSharedMemorySize, (int)sizeof(EdgeSmem));
    cudaFuncSetAttribute(out_kernel,  cudaFuncAttributeMaxDynamicSharedMemorySize, (int)sizeof(OutSmem));

    node_kernel<<<592, 256, sizeof(NodeSmem)>>>(x, W_in, b_in, W_src, W_dst, W_lin, b_lin, nn);
    edge_kernel<<<592, 256, sizeof(EdgeSmem)>>>(pos, ei, Wp1, bp1, Wp2, bp2, Wa1, ba1, Wa2, ba2, ne);
    out_kernel<<<592, 256, sizeof(OutSmem)>>>(W_out, b_out, out, nn);
}

// round 2
// speedup vs baseline: 1.0001x; 1.0001x over previous
#include <cuda_runtime.h>

#define NN_MAX 60000
#define EE_MAX 960000

// ---------------- scratch (static device allocations; no cudaMalloc) ----------------
__device__ float g_asrc[NN_MAX * 64];
__device__ float g_adst[NN_MAX * 64];
__device__ float g_v[NN_MAX * 64];
__device__ float g_nd[NN_MAX * 128];   // [node][0:64]=numerator, [64:128]=denominator

// ================= node kernel: h=relu(xWin+bin); a_src,a_dst,v; zero nd =================
struct NodeSmem {
    float Win[64 * 64], Ws[64 * 64], Wd[64 * 64], Wl[64 * 64];
    float bin[64], bl[64];
    float xs[8][64];
    float hs[8][64];
};

__global__ __launch_bounds__(256, 3) void node_kernel(
    const float* __restrict__ x,
    const float* __restrict__ Win, const float* __restrict__ bin,
    const float* __restrict__ Wsrc, const float* __restrict__ Wdst,
    const float* __restrict__ Wlin, const float* __restrict__ blin, int nn)
{
    extern __shared__ char smem_raw[];
    NodeSmem& s = *reinterpret_cast<NodeSmem*>(smem_raw);
    int tid = threadIdx.x;
    for (int i = tid; i < 4096; i += blockDim.x) {
        s.Win[i] = Win[i]; s.Ws[i] = Wsrc[i]; s.Wd[i] = Wdst[i]; s.Wl[i] = Wlin[i];
    }
    if (tid < 64) { s.bin[tid] = bin[tid]; s.bl[tid] = blin[tid]; }
    __syncthreads();

    int warp = tid >> 5, lane = tid & 31, c0 = lane * 2;
    int totW = (gridDim.x * blockDim.x) >> 5;
    for (int node = (blockIdx.x * blockDim.x + tid) >> 5; node < nn; node += totW) {
        float2 xv = *reinterpret_cast<const float2*>(&x[node * 64 + c0]);
        s.xs[warp][c0] = xv.x; s.xs[warp][c0 + 1] = xv.y;
        __syncwarp();
        float h0 = s.bin[c0], h1 = s.bin[c0 + 1];
        #pragma unroll 16
        for (int k = 0; k < 64; k++) {
            float xk = s.xs[warp][k];
            float2 w = *reinterpret_cast<float2*>(&s.Win[k * 64 + c0]);
            h0 = fmaf(xk, w.x, h0); h1 = fmaf(xk, w.y, h1);
        }
        h0 = fmaxf(h0, 0.f); h1 = fmaxf(h1, 0.f);
        __syncwarp();
        s.hs[warp][c0] = h0; s.hs[warp][c0 + 1] = h1;
        __syncwarp();
        float s0 = 0.f, s1 = 0.f, d0 = 0.f, d1 = 0.f;
        float v0 = s.bl[c0], v1 = s.bl[c0 + 1];
        #pragma unroll 16
        for (int k = 0; k < 64; k++) {
            float hk = s.hs[warp][k];
            float2 ws = *reinterpret_cast<float2*>(&s.Ws[k * 64 + c0]);
            float2 wd = *reinterpret_cast<float2*>(&s.Wd[k * 64 + c0]);
            float2 wl = *reinterpret_cast<float2*>(&s.Wl[k * 64 + c0]);
            s0 = fmaf(hk, ws.x, s0); s1 = fmaf(hk, ws.y, s1);
            d0 = fmaf(hk, wd.x, d0); d1 = fmaf(hk, wd.y, d1);
            v0 = fmaf(hk, wl.x, v0); v1 = fmaf(hk, wl.y, v1);
        }
        *reinterpret_cast<float2*>(&g_asrc[node * 64 + c0]) = make_float2(s0, s1);
        *reinterpret_cast<float2*>(&g_adst[node * 64 + c0]) = make_float2(d0, d1);
        *reinterpret_cast<float2*>(&g_v[node * 64 + c0])    = make_float2(v0, v1);
        *reinterpret_cast<float4*>(&g_nd[node * 128 + lane * 4]) = make_float4(0.f, 0.f, 0.f, 0.f);
        __syncwarp();
    }
}

// ================= edge kernel: fused delta-MLP, attn-MLP, exp, RED accumulate =================
#define NWARP 8
#define ME 8

struct EdgeSmem {
    float Wp1[3 * 64];
    float Wp2[64 * 64], Wa1[64 * 64], Wa2[64 * 64];
    float bp1[64], bp2[64], ba1[64], ba2[64];
    float X[NWARP][ME][64];   // h1 -> q -> t (reused between syncwarps)
    float D[NWARP][ME][64];   // delta
    int   srcs[NWARP][ME];
    int   dsts[NWARP][ME];
    float pd[NWARP][ME][3];
};

__global__ __launch_bounds__(256, 2) void edge_kernel(
    const float* __restrict__ pos, const int* __restrict__ ei,
    const float* __restrict__ Wp1, const float* __restrict__ bp1,
    const float* __restrict__ Wp2, const float* __restrict__ bp2,
    const float* __restrict__ Wa1, const float* __restrict__ ba1,
    const float* __restrict__ Wa2, const float* __restrict__ ba2, int ne)
{
    extern __shared__ char smem_raw[];
    EdgeSmem& s = *reinterpret_cast<EdgeSmem*>(smem_raw);
    int tid = threadIdx.x;
    for (int i = tid; i < 3 * 64; i += blockDim.x) s.Wp1[i] = Wp1[i];
    for (int i = tid; i < 4096; i += blockDim.x) {
        s.Wp2[i] = Wp2[i]; s.Wa1[i] = Wa1[i]; s.Wa2[i] = Wa2[i];
    }
    if (tid < 64) { s.bp1[tid] = bp1[tid]; s.bp2[tid] = bp2[tid]; s.ba1[tid] = ba1[tid]; s.ba2[tid] = ba2[tid]; }
    __syncthreads();

    int warp = tid >> 5, lane = tid & 31, c0 = lane * 2;
    int gw = blockIdx.x * NWARP + warp;
    int totW = gridDim.x * NWARP;
    int ngroups = (ne + ME - 1) / ME;

    for (int g = gw; g < ngroups; g += totW) {
        int e0 = g * ME;
        // ---- per-edge meta: indices + pos diff ----
        if (lane < ME) {
            int eidx = e0 + lane;
            int si = 0, di = 0;
            float p0 = 0.f, p1 = 0.f, p2 = 0.f;
            if (eidx < ne) {
                si = ei[eidx];
                di = ei[ne + eidx];
                p0 = pos[di * 3 + 0] - pos[si * 3 + 0];
                p1 = pos[di * 3 + 1] - pos[si * 3 + 1];
                p2 = pos[di * 3 + 2] - pos[si * 3 + 2];
            }
            s.srcs[warp][lane] = si; s.dsts[warp][lane] = di;
            s.pd[warp][lane][0] = p0; s.pd[warp][lane][1] = p1; s.pd[warp][lane][2] = p2;
        }
        __syncwarp();

        // ---- h1 = relu(pd @ Wp1 + bp1) ----
        {
            float b0 = s.bp1[c0], b1 = s.bp1[c0 + 1];
            float2 w0 = *reinterpret_cast<float2*>(&s.Wp1[0 * 64 + c0]);
            float2 w1 = *reinterpret_cast<float2*>(&s.Wp1[1 * 64 + c0]);
            float2 w2 = *reinterpret_cast<float2*>(&s.Wp1[2 * 64 + c0]);
            #pragma unroll
            for (int e = 0; e < ME; e++) {
                float p0 = s.pd[warp][e][0], p1 = s.pd[warp][e][1], p2 = s.pd[warp][e][2];
                float a0 = fmaf(p2, w2.x, fmaf(p1, w1.x, fmaf(p0, w0.x, b0)));
                float a1 = fmaf(p2, w2.y, fmaf(p1, w1.y, fmaf(p0, w0.y, b1)));
                s.X[warp][e][c0] = fmaxf(a0, 0.f);
                s.X[warp][e][c0 + 1] = fmaxf(a1, 0.f);
            }
        }
        // prefetch a_dst[dst], a_src[src] gathers (independent of delta matvec)
        float2 ad[ME], as[ME];
        #pragma unroll
        for (int e = 0; e < ME; e++) {
            int si = s.srcs[warp][e], di = s.dsts[warp][e];
            ad[e] = *reinterpret_cast<const float2*>(&g_adst[di * 64 + c0]);
            as[e] = *reinterpret_cast<const float2*>(&g_asrc[si * 64 + c0]);
        }
        __syncwarp();

        // ---- delta = relu(h1 @ Wp2 + bp2) ----
        float acc0[ME], acc1[ME];
        #pragma unroll
        for (int e = 0; e < ME; e++) { acc0[e] = 0.f; acc1[e] = 0.f; }
        #pragma unroll 8
        for (int k = 0; k < 64; k++) {
            float2 w = *reinterpret_cast<float2*>(&s.Wp2[k * 64 + c0]);
            #pragma unroll
            for (int e = 0; e < ME; e++) {
                float xk = s.X[warp][e][k];
                acc0[e] = fmaf(xk, w.x, acc0[e]);
                acc1[e] = fmaf(xk, w.y, acc1[e]);
            }
        }
        __syncwarp();
        #pragma unroll
        for (int e = 0; e < ME; e++) {
            float d0 = fmaxf(acc0[e] + s.bp2[c0], 0.f);
            float d1 = fmaxf(acc1[e] + s.bp2[c0 + 1], 0.f);
            s.D[warp][e][c0] = d0;  s.D[warp][e][c0 + 1] = d1;
            s.X[warp][e][c0]     = ad[e].x - as[e].x + d0;
            s.X[warp][e][c0 + 1] = ad[e].y - as[e].y + d1;
        }
        __syncwarp();

        // ---- t = relu(q @ Wa1 + ba1) ----
        #pragma unroll
        for (int e = 0; e < ME; e++) { acc0[e] = 0.f; acc1[e] = 0.f; }
        #pragma unroll 8
        for (int k = 0; k < 64; k++) {
            float2 w = *reinterpret_cast<float2*>(&s.Wa1[k * 64 + c0]);
            #pragma unroll
            for (int e = 0; e < ME; e++) {
                float xk = s.X[warp][e][k];
                acc0[e] = fmaf(xk, w.x, acc0[e]);
                acc1[e] = fmaf(xk, w.y, acc1[e]);
            }
        }
        __syncwarp();
        #pragma unroll
        for (int e = 0; e < ME; e++) {
            s.X[warp][e][c0]     = fmaxf(acc0[e] + s.ba1[c0], 0.f);
            s.X[warp][e][c0 + 1] = fmaxf(acc1[e] + s.ba1[c0 + 1], 0.f);
        }
        __syncwarp();

        // prefetch v[src]
        float2 vv[ME];
        #pragma unroll
        for (int e = 0; e < ME; e++) {
            int si = s.srcs[warp][e];
            vv[e] = *reinterpret_cast<const float2*>(&g_v[si * 64 + c0]);
        }

        // ---- a = relu(t @ Wa2 + ba2); p = exp(a); accumulate ----
        #pragma unroll
        for (int e = 0; e < ME; e++) { acc0[e] = 0.f; acc1[e] = 0.f; }
        #pragma unroll 8
        for (int k = 0; k < 64; k++) {
            float2 w = *reinterpret_cast<float2*>(&s.Wa2[k * 64 + c0]);
            #pragma unroll
            for (int e = 0; e < ME; e++) {
                float xk = s.X[warp][e][k];
                acc0[e] = fmaf(xk, w.x, acc0[e]);
                acc1[e] = fmaf(xk, w.y, acc1[e]);
            }
        }
        #pragma unroll
        for (int e = 0; e < ME; e++) {
            if (e0 + e < ne) {
                float a0 = fmaxf(acc0[e] + s.ba2[c0], 0.f);
                float a1 = fmaxf(acc1[e] + s.ba2[c0 + 1], 0.f);
                float p0 = __expf(a0), p1 = __expf(a1);
                float w0v = vv[e].x + s.D[warp][e][c0];
                float w1v = vv[e].y + s.D[warp][e][c0 + 1];
                int di = s.dsts[warp][e];
                float* nd = &g_nd[di * 128];
                atomicAdd(&nd[c0],      p0 * w0v);
                atomicAdd(&nd[c0 + 1],  p1 * w1v);
                atomicAdd(&nd[64 + c0],     p0);
                atomicAdd(&nd[64 + c0 + 1], p1);
            }
        }
        __syncwarp();   // protect meta/X/D reuse across group iterations
    }
}

// ================= out kernel: relu((num/den) @ W_out + b_out) =================
struct OutSmem {
    float W[64 * 64];
    float b[64];
    float rs[8][64];
};

__global__ __launch_bounds__(256, 3) void out_kernel(
    const float* __restrict__ Wout, const float* __restrict__ bout,
    float* __restrict__ out, int nn)
{
    extern __shared__ char smem_raw[];
    OutSmem& s = *reinterpret_cast<OutSmem*>(smem_raw);
    int tid = threadIdx.x;
    for (int i = tid; i < 4096; i += blockDim.x) s.W[i] = Wout[i];
    if (tid < 64) s.b[tid] = bout[tid];
    __syncthreads();

    int warp = tid >> 5, lane = tid & 31, c0 = lane * 2;
    int totW = (gridDim.x * blockDim.x) >> 5;
    for (int node = (blockIdx.x * blockDim.x + tid) >> 5; node < nn; node += totW) {
        float2 nm = *reinterpret_cast<float2*>(&g_nd[node * 128 + c0]);
        float2 dn = *reinterpret_cast<float2*>(&g_nd[node * 128 + 64 + c0]);
        float r0 = nm.x / (dn.x + 1e-16f);
        float r1 = nm.y / (dn.y + 1e-16f);
        s.rs[warp][c0] = r0; s.rs[warp][c0 + 1] = r1;
        __syncwarp();
        float o0 = s.b[c0], o1 = s.b[c0 + 1];
        #pragma unroll 16
        for (int k = 0; k < 64; k++) {
            float rk = s.rs[warp][k];
            float2 w = *reinterpret_cast<float2*>(&s.W[k * 64 + c0]);
            o0 = fmaf(rk, w.x, o0); o1 = fmaf(rk, w.y, o1);
        }
        *reinterpret_cast<float2*>(&out[node * 64 + c0]) =
            make_float2(fmaxf(o0, 0.f), fmaxf(o1, 0.f));
        __syncwarp();
    }
}

// ================= launch =================
extern "C" void kernel_launch(void* const* d_in, const int* in_sizes, int n_in,
                              void* d_out, int out_size)
{
    const float* x     = (const float*)d_in[0];
    const float* pos   = (const float*)d_in[1];
    const float* W_in  = (const float*)d_in[2];
    const float* b_in  = (const float*)d_in[3];
    const float* W_src = (const float*)d_in[4];
    const float* W_dst = (const float*)d_in[5];
    const float* W_lin = (const float*)d_in[6];
    const float* b_lin = (const float*)d_in[7];
    const float* Wp1   = (const float*)d_in[8];
    const float* bp1   = (const float*)d_in[9];
    const float* Wp2   = (const float*)d_in[10];
    const float* bp2   = (const float*)d_in[11];
    const float* Wa1   = (const float*)d_in[12];
    const float* ba1   = (const float*)d_in[13];
    const float* Wa2   = (const float*)d_in[14];
    const float* ba2   = (const float*)d_in[15];
    const float* W_out = (const float*)d_in[16];
    const float* b_out = (const float*)d_in[17];
    const int*   ei    = (const int*)d_in[18];
    float* out = (float*)d_out;

    int nn = in_sizes[0] / 64;
    int ne = in_sizes[18] / 2;

    cudaFuncSetAttribute(node_kernel, cudaFuncAttributeMaxDynamicSharedMemorySize, (int)sizeof(NodeSmem));
    cudaFuncSetAttribute(edge_kernel, cudaFuncAttributeMaxDynamicSharedMemorySize, (int)sizeof(EdgeSmem));
    cudaFuncSetAttribute(out_kernel,  cudaFuncAttributeMaxDynamicSharedMemorySize, (int)sizeof(OutSmem));

    node_kernel<<<592, 256, sizeof(NodeSmem)>>>(x, W_in, b_in, W_src, W_dst, W_lin, b_lin, nn);
    edge_kernel<<<592, 256, sizeof(EdgeSmem)>>>(pos, ei, Wp1, bp1, Wp2, bp2, Wa1, ba1, Wa2, ba2, ne);
    out_kernel<<<592, 256, sizeof(OutSmem)>>>(W_out, b_out, out, nn);
}